// round 1
// baseline (speedup 1.0000x reference)
#include <cuda_runtime.h>

#define BB 2
#define SS 2048
#define DD 1024
#define HH 16
#define HD 64
#define NROWS (BB*SS)

// Scratch (allocation-free rule: __device__ globals)
__device__ float g_q[NROWS*DD];    // [B,H,S,HD]
__device__ float g_k[NROWS*DD];    // [B,H,S,HD]
__device__ float g_v[NROWS*DD];    // [B,H,S,HD]
__device__ float g_ctx[NROWS*DD];  // [B,S,D]

#define BM 128
#define BN 128
#define BK 16

// ---------------------------------------------------------------------------
// Fused QKV GEMM: Y = X*W + b, scattered to [B,H,S,HD]. blockIdx.z selects q/k/v.
// ---------------------------------------------------------------------------
__global__ __launch_bounds__(256) void qkv_gemm(
    const float* __restrict__ X,
    const float* __restrict__ Wq, const float* __restrict__ bq,
    const float* __restrict__ Wk, const float* __restrict__ bk,
    const float* __restrict__ Wv, const float* __restrict__ bv)
{
    const int z = blockIdx.z;
    const float* __restrict__ W    = (z == 0) ? Wq : (z == 1) ? Wk : Wv;
    const float* __restrict__ bias = (z == 0) ? bq : (z == 1) ? bk : bv;
    float* __restrict__ out        = (z == 0) ? g_q : (z == 1) ? g_k : g_v;

    __shared__ float As[BK][BM];   // A stored transposed: As[k][m]
    __shared__ float Bs[BK][BN];

    const int tid = threadIdx.x;
    const int tx = tid & 15;       // 0..15
    const int ty = tid >> 4;       // 0..15
    const int rowBase = blockIdx.y * BM;
    const int colBase = blockIdx.x * BN;

    float acc[8][8];
#pragma unroll
    for (int i = 0; i < 8; i++)
#pragma unroll
        for (int j = 0; j < 8; j++) acc[i][j] = 0.f;

    for (int k0 = 0; k0 < DD; k0 += BK) {
        // Load A tile 128x16 (512 float4, 2 per thread), scatter transposed
#pragma unroll
        for (int i = 0; i < 2; i++) {
            int t  = tid + i * 256;
            int r  = t >> 2;            // 0..127
            int c4 = (t & 3) << 2;      // 0,4,8,12
            float4 a = *(const float4*)&X[(size_t)(rowBase + r) * DD + k0 + c4];
            As[c4 + 0][r] = a.x; As[c4 + 1][r] = a.y;
            As[c4 + 2][r] = a.z; As[c4 + 3][r] = a.w;
        }
        // Load B tile 16x128
#pragma unroll
        for (int i = 0; i < 2; i++) {
            int t  = tid + i * 256;
            int r  = t >> 5;            // 0..15
            int c4 = (t & 31) << 2;     // 0..124
            *(float4*)&Bs[r][c4] =
                *(const float4*)&W[(size_t)(k0 + r) * DD + colBase + c4];
        }
        __syncthreads();

#pragma unroll
        for (int kk = 0; kk < BK; kk++) {
            float ra[8], rb[8];
            // split 4+4 register blocking -> conflict-free LDS.128
            *(float4*)&ra[0] = *(const float4*)&As[kk][ty * 4];
            *(float4*)&ra[4] = *(const float4*)&As[kk][64 + ty * 4];
            *(float4*)&rb[0] = *(const float4*)&Bs[kk][tx * 4];
            *(float4*)&rb[4] = *(const float4*)&Bs[kk][64 + tx * 4];
#pragma unroll
            for (int i = 0; i < 8; i++)
#pragma unroll
                for (int j = 0; j < 8; j++) acc[i][j] += ra[i] * rb[j];
        }
        __syncthreads();
    }

    // Store: scatter to [B,H,S,HD] with bias
#pragma unroll
    for (int i = 0; i < 8; i++) {
        int n = rowBase + ty * 4 + (i & 3) + ((i >> 2) << 6);
        int b = n >> 11;            // /S
        int s = n & (SS - 1);
#pragma unroll
        for (int j = 0; j < 8; j++) {
            int c = colBase + tx * 4 + (j & 3) + ((j >> 2) << 6);
            int h = c >> 6;
            int d = c & 63;
            out[(((size_t)(b * HH + h)) * SS + s) * HD + d] = acc[i][j] + bias[c];
        }
    }
}

// ---------------------------------------------------------------------------
// Causal flash attention: 1 block per (b*h, 64-row q tile), 64 threads,
// one q-row per thread. K/V tiles staged in smem (broadcast reads).
// ---------------------------------------------------------------------------
__global__ __launch_bounds__(64) void attn_kernel()
{
    const int qt   = blockIdx.x;            // q tile index
    const int bh   = blockIdx.y;            // b*H + h
    const int tidx = threadIdx.x;           // 0..63
    const int qi   = qt * 64 + tidx;        // global q row in this head

    __shared__ float Ks[64][68];            // pad 4 to break store conflicts
    __shared__ float Vs[64][68];

    float q[HD], o[HD];
    const float* qrow = &g_q[((size_t)bh * SS + qi) * HD];
#pragma unroll
    for (int d = 0; d < HD; d += 4) {
        float4 t = *(const float4*)&qrow[d];
        q[d] = t.x * 0.125f; q[d + 1] = t.y * 0.125f;   // 1/sqrt(64)
        q[d + 2] = t.z * 0.125f; q[d + 3] = t.w * 0.125f;
    }
#pragma unroll
    for (int d = 0; d < HD; d++) o[d] = 0.f;
    float m = -1e30f, l = 0.f;

    const int ntiles = qt + 1;              // causal: only tiles <= qt
    for (int kt = 0; kt < ntiles; kt++) {
        const float* krow = &g_k[((size_t)bh * SS + kt * 64 + tidx) * HD];
        const float* vrow = &g_v[((size_t)bh * SS + kt * 64 + tidx) * HD];
#pragma unroll
        for (int d = 0; d < HD; d += 4) {
            *(float4*)&Ks[tidx][d] = *(const float4*)&krow[d];
            *(float4*)&Vs[tidx][d] = *(const float4*)&vrow[d];
        }
        __syncthreads();

        const int jmax = (kt < qt) ? 64 : (tidx + 1);   // causal mask
        for (int j = 0; j < jmax; j++) {
            float s = 0.f;
#pragma unroll
            for (int d = 0; d < HD; d += 4) {
                float4 kk = *(const float4*)&Ks[j][d];
                s += q[d] * kk.x + q[d + 1] * kk.y
                   + q[d + 2] * kk.z + q[d + 3] * kk.w;
            }
            float p;
            if (s > m) {
                float sc = __expf(m - s);
                l *= sc;
#pragma unroll
                for (int d = 0; d < HD; d++) o[d] *= sc;
                m = s;
                p = 1.f;
            } else {
                p = __expf(s - m);
            }
            l += p;
#pragma unroll
            for (int d = 0; d < HD; d += 4) {
                float4 vv = *(const float4*)&Vs[j][d];
                o[d]     += p * vv.x; o[d + 1] += p * vv.y;
                o[d + 2] += p * vv.z; o[d + 3] += p * vv.w;
            }
        }
        __syncthreads();
    }

    const float inv = 1.f / l;
    const int b = bh / HH;
    const int h = bh % HH;
    float* crow = &g_ctx[((size_t)b * SS + qi) * DD + h * HD];
#pragma unroll
    for (int d = 0; d < HD; d += 4) {
        float4 t;
        t.x = o[d] * inv; t.y = o[d + 1] * inv;
        t.z = o[d + 2] * inv; t.w = o[d + 3] * inv;
        *(float4*)&crow[d] = t;
    }
}

// ---------------------------------------------------------------------------
// Output projection: out = ctx*Wo + bo  (plain row-major store)
// ---------------------------------------------------------------------------
__global__ __launch_bounds__(256) void out_gemm(
    const float* __restrict__ Wo, const float* __restrict__ bo,
    float* __restrict__ Y)
{
    __shared__ float As[BK][BM];
    __shared__ float Bs[BK][BN];

    const int tid = threadIdx.x;
    const int tx = tid & 15;
    const int ty = tid >> 4;
    const int rowBase = blockIdx.y * BM;
    const int colBase = blockIdx.x * BN;

    float acc[8][8];
#pragma unroll
    for (int i = 0; i < 8; i++)
#pragma unroll
        for (int j = 0; j < 8; j++) acc[i][j] = 0.f;

    for (int k0 = 0; k0 < DD; k0 += BK) {
#pragma unroll
        for (int i = 0; i < 2; i++) {
            int t  = tid + i * 256;
            int r  = t >> 2;
            int c4 = (t & 3) << 2;
            float4 a = *(const float4*)&g_ctx[(size_t)(rowBase + r) * DD + k0 + c4];
            As[c4 + 0][r] = a.x; As[c4 + 1][r] = a.y;
            As[c4 + 2][r] = a.z; As[c4 + 3][r] = a.w;
        }
#pragma unroll
        for (int i = 0; i < 2; i++) {
            int t  = tid + i * 256;
            int r  = t >> 5;
            int c4 = (t & 31) << 2;
            *(float4*)&Bs[r][c4] =
                *(const float4*)&Wo[(size_t)(k0 + r) * DD + colBase + c4];
        }
        __syncthreads();

#pragma unroll
        for (int kk = 0; kk < BK; kk++) {
            float ra[8], rb[8];
            *(float4*)&ra[0] = *(const float4*)&As[kk][ty * 4];
            *(float4*)&ra[4] = *(const float4*)&As[kk][64 + ty * 4];
            *(float4*)&rb[0] = *(const float4*)&Bs[kk][tx * 4];
            *(float4*)&rb[4] = *(const float4*)&Bs[kk][64 + tx * 4];
#pragma unroll
            for (int i = 0; i < 8; i++)
#pragma unroll
                for (int j = 0; j < 8; j++) acc[i][j] += ra[i] * rb[j];
        }
        __syncthreads();
    }

#pragma unroll
    for (int i = 0; i < 8; i++) {
        int n = rowBase + ty * 4 + (i & 3) + ((i >> 2) << 6);
#pragma unroll
        for (int j = 0; j < 8; j++) {
            int c = colBase + tx * 4 + (j & 3) + ((j >> 2) << 6);
            Y[(size_t)n * DD + c] = acc[i][j] + bo[c];
        }
    }
}

// ---------------------------------------------------------------------------
extern "C" void kernel_launch(void* const* d_in, const int* in_sizes, int n_in,
                              void* d_out, int out_size)
{
    const float* x  = (const float*)d_in[0];
    const float* Wq = (const float*)d_in[1];
    const float* bq = (const float*)d_in[2];
    const float* Wk = (const float*)d_in[3];
    const float* bk = (const float*)d_in[4];
    const float* Wv = (const float*)d_in[5];
    const float* bv = (const float*)d_in[6];
    const float* Wo = (const float*)d_in[7];
    const float* bo = (const float*)d_in[8];
    float* out = (float*)d_out;

    dim3 gqkv(DD / BN, NROWS / BM, 3);         // (8, 32, 3)
    qkv_gemm<<<gqkv, 256>>>(x, Wq, bq, Wk, bk, Wv, bv);

    dim3 gattn(SS / 64, BB * HH);              // (32, 32)
    attn_kernel<<<gattn, 64>>>();

    dim3 gout(DD / BN, NROWS / BM);            // (8, 32)
    out_gemm<<<gout, 256>>>(Wo, bo, out);
}

// round 5
// speedup vs baseline: 1.0744x; 1.0744x over previous
#include <cuda_runtime.h>
#include <cstdint>
#include <mma.h>

using namespace nvcuda;

#define BB 2
#define SS 2048
#define DD 1024
#define HH 16
#define HD 64
#define NROWS (BB*SS)

// ---------------------------------------------------------------------------
// Scratch (allocation-free rule: __device__ globals)
// ---------------------------------------------------------------------------
__device__ float g_q[NROWS*DD];        // [B,H,S,HD]
__device__ float g_k[NROWS*DD];        // [B,H,S,HD]
__device__ float g_v[NROWS*DD];        // [B,H,S,HD]
__device__ float g_ctx[NROWS*DD];      // [B,S,D]

// ---------------------------------------------------------------------------
// Helpers
// ---------------------------------------------------------------------------
__device__ __forceinline__ uint32_t smem_u32(const void* p) {
    uint32_t a;
    asm("{ .reg .u64 t; cvta.to.shared.u64 t, %1; cvt.u32.u64 %0, t; }" : "=r"(a) : "l"(p));
    return a;
}
#define CP_ASYNC16(s, g) \
    asm volatile("cp.async.cg.shared.global [%0], [%1], 16;" :: "r"(s), "l"(g))
#define CP_COMMIT() asm volatile("cp.async.commit_group;")
#define CP_WAIT0()  asm volatile("cp.async.wait_group 0;" ::: "memory")

// ---------------------------------------------------------------------------
// tf32 WMMA GEMM: C[4096 x 1024] = A @ W + bias
// CTA 128x128, BK=32, 256 thr, 8 warps (2 m x 4 n), warp tile 64x32.
// A smem [m][k] stride 36; B smem [k][n] stride 136. cp.async double buffer.
// Epilogue stages C in (reused) smem, then bias + scatter/store.
// SCATTER=true : A = x (arg), out = g_q/g_k/g_v scattered [B,H,S,HD]
// SCATTER=false: A = g_ctx (DEVICE-side binding!), out = Yout row-major
// ---------------------------------------------------------------------------
#define AS_STRIDE 36
#define BS_STRIDE 136
#define AS_FLOATS (128 * AS_STRIDE)          // 4608
#define BS_FLOATS (32 * BS_STRIDE)           // 4352
#define SMEM_FLOATS (2 * (AS_FLOATS + BS_FLOATS))
#define SMEM_BYTES  (SMEM_FLOATS * 4)        // 71680
#define ST_STRIDE 132                        // epilogue staging 128x132 floats

template<bool SCATTER>
__global__ __launch_bounds__(256) void gemm_wmma(
    const float* __restrict__ Ain,
    const float* __restrict__ W0, const float* __restrict__ W1, const float* __restrict__ W2,
    const float* __restrict__ bi0, const float* __restrict__ bi1, const float* __restrict__ bi2,
    float* __restrict__ Yout)
{
    extern __shared__ float smem[];
    float* sA = smem;                        // 2 x AS_FLOATS
    float* sB = smem + 2 * AS_FLOATS;        // 2 x BS_FLOATS

    const int tid  = threadIdx.x;
    const int wid  = tid >> 5;
    const int wm   = wid & 1;                // m offset *64
    const int wn   = wid >> 1;               // n offset *32

    // Device-side pointer binding (NEVER pass __device__ globals from host!)
    const float* __restrict__ A = SCATTER ? Ain : g_ctx;
    const float* __restrict__ W;
    const float* __restrict__ bias;
    float* __restrict__ outp;
    if (SCATTER) {
        const int z = blockIdx.z;
        W    = (z == 0) ? W0 : (z == 1) ? W1 : W2;
        bias = (z == 0) ? bi0 : (z == 1) ? bi1 : bi2;
        outp = (z == 0) ? g_q : (z == 1) ? g_k : g_v;
    } else {
        W = W0; bias = bi0; outp = Yout;
    }

    const int rowBase = blockIdx.y * 128;
    const int colBase = blockIdx.x * 128;

    wmma::fragment<wmma::accumulator, 16, 16, 8, float> acc[4][2];
#pragma unroll
    for (int mt = 0; mt < 4; mt++)
#pragma unroll
        for (int nt = 0; nt < 2; nt++)
            wmma::fill_fragment(acc[mt][nt], 0.f);

    const uint32_t sAu = smem_u32(sA);
    const uint32_t sBu = smem_u32(sB);

    auto load_tile = [&](int it, int buf) {
        const int k0 = it * 32;
        uint32_t aBase = sAu + buf * AS_FLOATS * 4;
        uint32_t bBase = sBu + buf * BS_FLOATS * 4;
#pragma unroll
        for (int i = 0; i < 4; i++) {
            int ch = tid + i * 256;
            int m = ch >> 3, kq = ch & 7;
            CP_ASYNC16(aBase + (m * AS_STRIDE + kq * 4) * 4,
                       &A[(size_t)(rowBase + m) * DD + k0 + kq * 4]);
        }
#pragma unroll
        for (int i = 0; i < 4; i++) {
            int ch = tid + i * 256;
            int kk = ch >> 5, nq = ch & 31;
            CP_ASYNC16(bBase + (kk * BS_STRIDE + nq * 4) * 4,
                       &W[(size_t)(k0 + kk) * DD + colBase + nq * 4]);
        }
        CP_COMMIT();
    };

    load_tile(0, 0);
    CP_WAIT0();
    __syncthreads();

    const int NT = DD / 32;                  // 32
    for (int it = 0; it < NT; it++) {
        const int buf = it & 1;
        if (it + 1 < NT) load_tile(it + 1, buf ^ 1);

        const float* As = sA + buf * AS_FLOATS;
        const float* Bs = sB + buf * BS_FLOATS;

#pragma unroll
        for (int ks = 0; ks < 4; ks++) {
            const int k = ks * 8;
            wmma::fragment<wmma::matrix_a, 16, 16, 8, wmma::precision::tf32, wmma::row_major> af[4];
            wmma::fragment<wmma::matrix_b, 16, 16, 8, wmma::precision::tf32, wmma::row_major> bf[2];
#pragma unroll
            for (int mt = 0; mt < 4; mt++) {
                wmma::load_matrix_sync(af[mt], As + (wm * 64 + mt * 16) * AS_STRIDE + k, AS_STRIDE);
#pragma unroll
                for (int e = 0; e < af[mt].num_elements; e++)
                    af[mt].x[e] = wmma::__float_to_tf32(af[mt].x[e]);
            }
#pragma unroll
            for (int nt = 0; nt < 2; nt++) {
                wmma::load_matrix_sync(bf[nt], Bs + k * BS_STRIDE + wn * 32 + nt * 16, BS_STRIDE);
#pragma unroll
                for (int e = 0; e < bf[nt].num_elements; e++)
                    bf[nt].x[e] = wmma::__float_to_tf32(bf[nt].x[e]);
            }
#pragma unroll
            for (int mt = 0; mt < 4; mt++)
#pragma unroll
                for (int nt = 0; nt < 2; nt++)
                    wmma::mma_sync(acc[mt][nt], af[mt], bf[nt], acc[mt][nt]);
        }

        if (it + 1 < NT) CP_WAIT0();
        __syncthreads();
    }

    // Epilogue: stage C in reused smem, then bias + store
    float* stage = smem;   // 128 x ST_STRIDE floats
#pragma unroll
    for (int mt = 0; mt < 4; mt++)
#pragma unroll
        for (int nt = 0; nt < 2; nt++)
            wmma::store_matrix_sync(stage + (wm * 64 + mt * 16) * ST_STRIDE + wn * 32 + nt * 16,
                                    acc[mt][nt], ST_STRIDE, wmma::mem_row_major);
    __syncthreads();

    const int rr   = tid >> 1;               // 0..127
    const int half = tid & 1;                // 0..1 (64 cols each)
    const int row  = rowBase + rr;
    const int bb   = row >> 11;
    const int s    = row & (SS - 1);
    if (SCATTER) {
        const int colG = colBase + half * 64;
        const int h = colG >> 6;
        float* dst = &outp[(((size_t)(bb * HH + h)) * SS + s) * HD];
#pragma unroll
        for (int j = 0; j < 16; j++) {
            const int cl = half * 64 + j * 4;
            float4 v  = *(const float4*)&stage[rr * ST_STRIDE + cl];
            float4 bv = *(const float4*)&bias[colBase + cl];
            v.x += bv.x; v.y += bv.y; v.z += bv.z; v.w += bv.w;
            *(float4*)&dst[j * 4] = v;
        }
    } else {
        float* dst = &outp[(size_t)row * DD + colBase];
#pragma unroll
        for (int j = 0; j < 16; j++) {
            const int cl = half * 64 + j * 4;
            float4 v  = *(const float4*)&stage[rr * ST_STRIDE + cl];
            float4 bv = *(const float4*)&bias[colBase + cl];
            v.x += bv.x; v.y += bv.y; v.z += bv.z; v.w += bv.w;
            *(float4*)&dst[cl] = v;
        }
    }
}

// ---------------------------------------------------------------------------
// Causal flash attention (SIMT): 1 block per (b*h, 64 q rows)
// ---------------------------------------------------------------------------
__global__ __launch_bounds__(64) void attn_kernel()
{
    const int qt   = blockIdx.x;
    const int bh   = blockIdx.y;
    const int tidx = threadIdx.x;
    const int qi   = qt * 64 + tidx;

    __shared__ float Ks[64][68];
    __shared__ float Vs[64][68];

    float q[HD], o[HD];
    const float* qrow = &g_q[((size_t)bh * SS + qi) * HD];
#pragma unroll
    for (int d = 0; d < HD; d += 4) {
        float4 t = *(const float4*)&qrow[d];
        q[d] = t.x * 0.125f; q[d + 1] = t.y * 0.125f;
        q[d + 2] = t.z * 0.125f; q[d + 3] = t.w * 0.125f;
    }
#pragma unroll
    for (int d = 0; d < HD; d++) o[d] = 0.f;
    float m = -1e30f, l = 0.f;

    const int ntiles = qt + 1;
    for (int kt = 0; kt < ntiles; kt++) {
        const float* krow = &g_k[((size_t)bh * SS + kt * 64 + tidx) * HD];
        const float* vrow = &g_v[((size_t)bh * SS + kt * 64 + tidx) * HD];
#pragma unroll
        for (int d = 0; d < HD; d += 4) {
            *(float4*)&Ks[tidx][d] = *(const float4*)&krow[d];
            *(float4*)&Vs[tidx][d] = *(const float4*)&vrow[d];
        }
        __syncthreads();

        const int jmax = (kt < qt) ? 64 : (tidx + 1);
        for (int j = 0; j < jmax; j++) {
            float s = 0.f;
#pragma unroll
            for (int d = 0; d < HD; d += 4) {
                float4 kk = *(const float4*)&Ks[j][d];
                s += q[d] * kk.x + q[d + 1] * kk.y
                   + q[d + 2] * kk.z + q[d + 3] * kk.w;
            }
            float p;
            if (s > m) {
                float sc = __expf(m - s);
                l *= sc;
#pragma unroll
                for (int d = 0; d < HD; d++) o[d] *= sc;
                m = s;
                p = 1.f;
            } else {
                p = __expf(s - m);
            }
            l += p;
#pragma unroll
            for (int d = 0; d < HD; d += 4) {
                float4 vv = *(const float4*)&Vs[j][d];
                o[d]     += p * vv.x; o[d + 1] += p * vv.y;
                o[d + 2] += p * vv.z; o[d + 3] += p * vv.w;
            }
        }
        __syncthreads();
    }

    const float inv = 1.f / l;
    const int b = bh / HH;
    const int h = bh % HH;
    float* crow = &g_ctx[((size_t)b * SS + qi) * DD + h * HD];
#pragma unroll
    for (int d = 0; d < HD; d += 4) {
        float4 t;
        t.x = o[d] * inv; t.y = o[d + 1] * inv;
        t.z = o[d + 2] * inv; t.w = o[d + 3] * inv;
        *(float4*)&crow[d] = t;
    }
}

// ---------------------------------------------------------------------------
extern "C" void kernel_launch(void* const* d_in, const int* in_sizes, int n_in,
                              void* d_out, int out_size)
{
    const float* x  = (const float*)d_in[0];
    const float* Wq = (const float*)d_in[1];
    const float* bq = (const float*)d_in[2];
    const float* Wk = (const float*)d_in[3];
    const float* bk = (const float*)d_in[4];
    const float* Wv = (const float*)d_in[5];
    const float* bv = (const float*)d_in[6];
    const float* Wo = (const float*)d_in[7];
    const float* bo = (const float*)d_in[8];
    float* out = (float*)d_out;

    cudaFuncSetAttribute(gemm_wmma<true>,  cudaFuncAttributeMaxDynamicSharedMemorySize, SMEM_BYTES);
    cudaFuncSetAttribute(gemm_wmma<false>, cudaFuncAttributeMaxDynamicSharedMemorySize, SMEM_BYTES);

    dim3 gqkv(DD / 128, NROWS / 128, 3);      // (8, 32, 3)
    gemm_wmma<true><<<gqkv, 256, SMEM_BYTES>>>(x, Wq, Wk, Wv, bq, bk, bv, nullptr);

    dim3 gattn(SS / 64, BB * HH);             // (32, 32)
    attn_kernel<<<gattn, 64>>>();

    dim3 gout(DD / 128, NROWS / 128);         // (8, 32)
    // A is bound to g_ctx INSIDE the kernel (SCATTER=false); first arg unused.
    gemm_wmma<false><<<gout, 256, SMEM_BYTES>>>(nullptr, Wo, nullptr, nullptr, bo, nullptr, nullptr, out);
}

// round 7
// speedup vs baseline: 1.5468x; 1.4397x over previous
#include <cuda_runtime.h>
#include <cstdint>
#include <mma.h>

using namespace nvcuda;

#define BB 2
#define SS 2048
#define DD 1024
#define HH 16
#define HD 64
#define NROWS (BB*SS)

__device__ float g_q[NROWS*DD];        // [B,H,S,HD]
__device__ float g_k[NROWS*DD];        // [B,H,S,HD]
__device__ float g_v[NROWS*DD];        // [B,H,S,HD]
__device__ float g_ctx[NROWS*DD];      // [B,S,D]

__device__ __forceinline__ uint32_t smem_u32(const void* p) {
    uint32_t a;
    asm("{ .reg .u64 t; cvta.to.shared.u64 t, %1; cvt.u32.u64 %0, t; }" : "=r"(a) : "l"(p));
    return a;
}
#define CP_ASYNC16(s, g) \
    asm volatile("cp.async.cg.shared.global [%0], [%1], 16;" :: "r"(s), "l"(g))
#define CP_COMMIT() asm volatile("cp.async.commit_group;")
#define CP_WAIT0()  asm volatile("cp.async.wait_group 0;" ::: "memory")

// ---------------------------------------------------------------------------
// tf32 WMMA GEMM (as R5, plus minBlocks=2 for occupancy)
// ---------------------------------------------------------------------------
#define AS_STRIDE 36
#define BS_STRIDE 136
#define AS_FLOATS (128 * AS_STRIDE)
#define BS_FLOATS (32 * BS_STRIDE)
#define SMEM_BYTES  (2 * (AS_FLOATS + BS_FLOATS) * 4)   // 71680
#define ST_STRIDE 132

template<bool SCATTER>
__global__ __launch_bounds__(256, 2) void gemm_wmma(
    const float* __restrict__ Ain,
    const float* __restrict__ W0, const float* __restrict__ W1, const float* __restrict__ W2,
    const float* __restrict__ bi0, const float* __restrict__ bi1, const float* __restrict__ bi2,
    float* __restrict__ Yout)
{
    extern __shared__ float smem[];
    float* sA = smem;
    float* sB = smem + 2 * AS_FLOATS;

    const int tid  = threadIdx.x;
    const int wid  = tid >> 5;
    const int wm   = wid & 1;
    const int wn   = wid >> 1;

    const float* __restrict__ A = SCATTER ? Ain : g_ctx;   // device-side binding!
    const float* __restrict__ W;
    const float* __restrict__ bias;
    float* __restrict__ outp;
    if (SCATTER) {
        const int z = blockIdx.z;
        W    = (z == 0) ? W0 : (z == 1) ? W1 : W2;
        bias = (z == 0) ? bi0 : (z == 1) ? bi1 : bi2;
        outp = (z == 0) ? g_q : (z == 1) ? g_k : g_v;
    } else {
        W = W0; bias = bi0; outp = Yout;
    }

    const int rowBase = blockIdx.y * 128;
    const int colBase = blockIdx.x * 128;

    wmma::fragment<wmma::accumulator, 16, 16, 8, float> acc[4][2];
#pragma unroll
    for (int mt = 0; mt < 4; mt++)
#pragma unroll
        for (int nt = 0; nt < 2; nt++)
            wmma::fill_fragment(acc[mt][nt], 0.f);

    const uint32_t sAu = smem_u32(sA);
    const uint32_t sBu = smem_u32(sB);

    auto load_tile = [&](int it, int buf) {
        const int k0 = it * 32;
        uint32_t aBase = sAu + buf * AS_FLOATS * 4;
        uint32_t bBase = sBu + buf * BS_FLOATS * 4;
#pragma unroll
        for (int i = 0; i < 4; i++) {
            int ch = tid + i * 256;
            int m = ch >> 3, kq = ch & 7;
            CP_ASYNC16(aBase + (m * AS_STRIDE + kq * 4) * 4,
                       &A[(size_t)(rowBase + m) * DD + k0 + kq * 4]);
        }
#pragma unroll
        for (int i = 0; i < 4; i++) {
            int ch = tid + i * 256;
            int kk = ch >> 5, nq = ch & 31;
            CP_ASYNC16(bBase + (kk * BS_STRIDE + nq * 4) * 4,
                       &W[(size_t)(k0 + kk) * DD + colBase + nq * 4]);
        }
        CP_COMMIT();
    };

    load_tile(0, 0);
    CP_WAIT0();
    __syncthreads();

    const int NT = DD / 32;
    for (int it = 0; it < NT; it++) {
        const int buf = it & 1;
        if (it + 1 < NT) load_tile(it + 1, buf ^ 1);

        const float* As = sA + buf * AS_FLOATS;
        const float* Bs = sB + buf * BS_FLOATS;

#pragma unroll
        for (int ks = 0; ks < 4; ks++) {
            const int k = ks * 8;
            wmma::fragment<wmma::matrix_a, 16, 16, 8, wmma::precision::tf32, wmma::row_major> af[4];
            wmma::fragment<wmma::matrix_b, 16, 16, 8, wmma::precision::tf32, wmma::row_major> bf[2];
#pragma unroll
            for (int mt = 0; mt < 4; mt++) {
                wmma::load_matrix_sync(af[mt], As + (wm * 64 + mt * 16) * AS_STRIDE + k, AS_STRIDE);
#pragma unroll
                for (int e = 0; e < af[mt].num_elements; e++)
                    af[mt].x[e] = wmma::__float_to_tf32(af[mt].x[e]);
            }
#pragma unroll
            for (int nt = 0; nt < 2; nt++) {
                wmma::load_matrix_sync(bf[nt], Bs + k * BS_STRIDE + wn * 32 + nt * 16, BS_STRIDE);
#pragma unroll
                for (int e = 0; e < bf[nt].num_elements; e++)
                    bf[nt].x[e] = wmma::__float_to_tf32(bf[nt].x[e]);
            }
#pragma unroll
            for (int mt = 0; mt < 4; mt++)
#pragma unroll
                for (int nt = 0; nt < 2; nt++)
                    wmma::mma_sync(acc[mt][nt], af[mt], bf[nt], acc[mt][nt]);
        }

        if (it + 1 < NT) CP_WAIT0();
        __syncthreads();
    }

    float* stage = smem;
#pragma unroll
    for (int mt = 0; mt < 4; mt++)
#pragma unroll
        for (int nt = 0; nt < 2; nt++)
            wmma::store_matrix_sync(stage + (wm * 64 + mt * 16) * ST_STRIDE + wn * 32 + nt * 16,
                                    acc[mt][nt], ST_STRIDE, wmma::mem_row_major);
    __syncthreads();

    const int rr   = tid >> 1;
    const int half = tid & 1;
    const int row  = rowBase + rr;
    const int bb   = row >> 11;
    const int s    = row & (SS - 1);
    if (SCATTER) {
        const int colG = colBase + half * 64;
        const int h = colG >> 6;
        float* dst = &outp[(((size_t)(bb * HH + h)) * SS + s) * HD];
#pragma unroll
        for (int j = 0; j < 16; j++) {
            const int cl = half * 64 + j * 4;
            float4 v  = *(const float4*)&stage[rr * ST_STRIDE + cl];
            float4 bv = *(const float4*)&bias[colBase + cl];
            v.x += bv.x; v.y += bv.y; v.z += bv.z; v.w += bv.w;
            *(float4*)&dst[j * 4] = v;
        }
    } else {
        float* dst = &outp[(size_t)row * DD + colBase];
#pragma unroll
        for (int j = 0; j < 16; j++) {
            const int cl = half * 64 + j * 4;
            float4 v  = *(const float4*)&stage[rr * ST_STRIDE + cl];
            float4 bv = *(const float4*)&bias[colBase + cl];
            v.x += bv.x; v.y += bv.y; v.z += bv.z; v.w += bv.w;
            *(float4*)&dst[cl] = v;
        }
    }
}

// ---------------------------------------------------------------------------
// Tensor-core causal flash attention.
// CTA = (qt, bh): 64 q rows, 128 threads (4 warps: warp w owns rows w*16..+15).
// Q frags held in registers across all k-tiles. S staged in smem; SIMT online
// softmax (64 threads, one row each); O in smem, accumulated via wmma with
// load-back C fragments.
// ---------------------------------------------------------------------------
#define ATS 72                     // smem row stride (multiple of 8)
#define ATT_TILE_F (64 * ATS)      // 4608 floats
#define ATT_SMEM_BYTES ((5 * ATT_TILE_F + 128) * 4)   // 92672

__global__ __launch_bounds__(128) void attn_wmma()
{
    extern __shared__ float sm[];
    float* Qs = sm;
    float* Ks = Qs + ATT_TILE_F;
    float* Vs = Ks + ATT_TILE_F;
    float* SP = Vs + ATT_TILE_F;
    float* Os = SP + ATT_TILE_F;
    float* mrow = Os + ATT_TILE_F;   // 64
    float* lrow = mrow + 64;         // 64

    const int qt  = blockIdx.x;
    const int bh  = blockIdx.y;
    const int tid = threadIdx.x;
    const int wid = tid >> 5;

    // Load Q (scaled by 1/sqrt(64)), zero O, init m/l
    const float* qbase = &g_q[((size_t)bh * SS + qt * 64) * HD];
    for (int i = tid; i < 1024; i += 128) {          // 64 rows x 16 float4
        int r = i >> 4, c4 = (i & 15) * 4;
        float4 v = *(const float4*)&qbase[r * HD + c4];
        v.x *= 0.125f; v.y *= 0.125f; v.z *= 0.125f; v.w *= 0.125f;
        *(float4*)&Qs[r * ATS + c4] = v;
        float4 z = {0.f, 0.f, 0.f, 0.f};
        *(float4*)&Os[r * ATS + c4] = z;
    }
    if (tid < 64) { mrow[tid] = -1e30f; lrow[tid] = 0.f; }
    __syncthreads();

    // Q fragments: rows wid*16, 8 k-steps — loaded ONCE
    wmma::fragment<wmma::matrix_a, 16, 16, 8, wmma::precision::tf32, wmma::row_major> qf[8];
#pragma unroll
    for (int ks = 0; ks < 8; ks++) {
        wmma::load_matrix_sync(qf[ks], Qs + (wid * 16) * ATS + ks * 8, ATS);
#pragma unroll
        for (int e = 0; e < qf[ks].num_elements; e++)
            qf[ks].x[e] = wmma::__float_to_tf32(qf[ks].x[e]);
    }

    for (int kt = 0; kt <= qt; kt++) {
        // Load K/V tile
        const float* kbase = &g_k[((size_t)bh * SS + kt * 64) * HD];
        const float* vbase = &g_v[((size_t)bh * SS + kt * 64) * HD];
        for (int i = tid; i < 1024; i += 128) {
            int r = i >> 4, c4 = (i & 15) * 4;
            *(float4*)&Ks[r * ATS + c4] = *(const float4*)&kbase[r * HD + c4];
            *(float4*)&Vs[r * ATS + c4] = *(const float4*)&vbase[r * HD + c4];
        }
        __syncthreads();

        // S = Q @ K^T   (B = K as col_major — no transpose needed)
        {
            wmma::fragment<wmma::accumulator, 16, 16, 8, float> sacc[4];
#pragma unroll
            for (int nt = 0; nt < 4; nt++) wmma::fill_fragment(sacc[nt], 0.f);
#pragma unroll
            for (int ks = 0; ks < 8; ks++) {
#pragma unroll
                for (int nt = 0; nt < 4; nt++) {
                    wmma::fragment<wmma::matrix_b, 16, 16, 8, wmma::precision::tf32, wmma::col_major> kf;
                    wmma::load_matrix_sync(kf, Ks + (nt * 16) * ATS + ks * 8, ATS);
#pragma unroll
                    for (int e = 0; e < kf.num_elements; e++)
                        kf.x[e] = wmma::__float_to_tf32(kf.x[e]);
                    wmma::mma_sync(sacc[nt], qf[ks], kf, sacc[nt]);
                }
            }
#pragma unroll
            for (int nt = 0; nt < 4; nt++)
                wmma::store_matrix_sync(SP + (wid * 16) * ATS + nt * 16, sacc[nt],
                                        ATS, wmma::mem_row_major);
        }
        __syncthreads();

        // Online softmax: one thread per row
        if (tid < 64) {
            const int row = tid;
            float* srow = SP + row * ATS;
            const int jmax = (kt == qt) ? (row + 1) : 64;
            float mx = mrow[row];
            const float mold = mx;
#pragma unroll 8
            for (int j = 0; j < jmax; j++) mx = fmaxf(mx, srow[j]);
            const float alpha = __expf(mold - mx);
            float sum = 0.f;
#pragma unroll 8
            for (int j = 0; j < 64; j++) {
                float p = (j < jmax) ? __expf(srow[j] - mx) : 0.f;
                srow[j] = p;
                sum += p;
            }
            lrow[row] = lrow[row] * alpha + sum;
            mrow[row] = mx;
            float* orow = Os + row * ATS;
#pragma unroll
            for (int d = 0; d < 64; d += 4) {
                float4 o4 = *(float4*)&orow[d];
                o4.x *= alpha; o4.y *= alpha; o4.z *= alpha; o4.w *= alpha;
                *(float4*)&orow[d] = o4;
            }
        }
        __syncthreads();

        // O += P @ V
        {
            wmma::fragment<wmma::matrix_a, 16, 16, 8, wmma::precision::tf32, wmma::row_major> pf[8];
#pragma unroll
            for (int ks = 0; ks < 8; ks++) {
                wmma::load_matrix_sync(pf[ks], SP + (wid * 16) * ATS + ks * 8, ATS);
#pragma unroll
                for (int e = 0; e < pf[ks].num_elements; e++)
                    pf[ks].x[e] = wmma::__float_to_tf32(pf[ks].x[e]);
            }
#pragma unroll
            for (int nt = 0; nt < 4; nt++) {
                wmma::fragment<wmma::accumulator, 16, 16, 8, float> of;
                wmma::load_matrix_sync(of, Os + (wid * 16) * ATS + nt * 16, ATS, wmma::mem_row_major);
#pragma unroll
                for (int ks = 0; ks < 8; ks++) {
                    wmma::fragment<wmma::matrix_b, 16, 16, 8, wmma::precision::tf32, wmma::row_major> vf;
                    wmma::load_matrix_sync(vf, Vs + (ks * 8) * ATS + nt * 16, ATS);
#pragma unroll
                    for (int e = 0; e < vf.num_elements; e++)
                        vf.x[e] = wmma::__float_to_tf32(vf.x[e]);
                    wmma::mma_sync(of, pf[ks], vf, of);
                }
                wmma::store_matrix_sync(Os + (wid * 16) * ATS + nt * 16, of, ATS, wmma::mem_row_major);
            }
        }
        __syncthreads();
    }

    // Normalize + write ctx: thread t -> row t>>1, cols (t&1)*32..+31
    const int row  = tid >> 1;
    const int half = tid & 1;
    const float inv = 1.f / lrow[row];
    const int b = bh / HH, h = bh % HH;
    float* crow = &g_ctx[((size_t)b * SS + qt * 64 + row) * DD + h * HD + half * 32];
    const float* orow = Os + row * ATS + half * 32;
#pragma unroll
    for (int d = 0; d < 32; d += 4) {
        float4 o4 = *(const float4*)&orow[d];
        o4.x *= inv; o4.y *= inv; o4.z *= inv; o4.w *= inv;
        *(float4*)&crow[d] = o4;
    }
}

// ---------------------------------------------------------------------------
extern "C" void kernel_launch(void* const* d_in, const int* in_sizes, int n_in,
                              void* d_out, int out_size)
{
    const float* x  = (const float*)d_in[0];
    const float* Wq = (const float*)d_in[1];
    const float* bq = (const float*)d_in[2];
    const float* Wk = (const float*)d_in[3];
    const float* bk = (const float*)d_in[4];
    const float* Wv = (const float*)d_in[5];
    const float* bv = (const float*)d_in[6];
    const float* Wo = (const float*)d_in[7];
    const float* bo = (const float*)d_in[8];
    float* out = (float*)d_out;

    cudaFuncSetAttribute(gemm_wmma<true>,  cudaFuncAttributeMaxDynamicSharedMemorySize, SMEM_BYTES);
    cudaFuncSetAttribute(gemm_wmma<false>, cudaFuncAttributeMaxDynamicSharedMemorySize, SMEM_BYTES);
    cudaFuncSetAttribute(attn_wmma, cudaFuncAttributeMaxDynamicSharedMemorySize, ATT_SMEM_BYTES);

    dim3 gqkv(DD / 128, NROWS / 128, 3);
    gemm_wmma<true><<<gqkv, 256, SMEM_BYTES>>>(x, Wq, Wk, Wv, bq, bk, bv, nullptr);

    dim3 gattn(SS / 64, BB * HH);             // (32, 32)
    attn_wmma<<<gattn, 128, ATT_SMEM_BYTES>>>();

    dim3 gout(DD / 128, NROWS / 128);
    gemm_wmma<false><<<gout, 256, SMEM_BYTES>>>(nullptr, Wo, nullptr, nullptr, bo, nullptr, nullptr, out);
}

// round 10
// speedup vs baseline: 1.5765x; 1.0192x over previous
#include <cuda_runtime.h>
#include <cstdint>
#include <mma.h>

using namespace nvcuda;

#define BB 2
#define SS 2048
#define DD 1024
#define HH 16
#define HD 64
#define NROWS (BB*SS)

__device__ float g_q[NROWS*DD];        // [B,H,S,HD]  (tf32-rounded)
__device__ float g_k[NROWS*DD];        // [B,H,S,HD]  (tf32-rounded)
__device__ float g_v[NROWS*DD];        // [B,H,S,HD]  (tf32-rounded)
__device__ float g_ctx[NROWS*DD];      // [B,S,D]     (tf32-rounded)
__device__ float g_xt[NROWS*DD];       // tf32(x)
__device__ float g_wt4[4*DD*DD];       // tf32(Wq,Wk,Wv,Wo)

__device__ __forceinline__ uint32_t smem_u32(const void* p) {
    uint32_t a;
    asm("{ .reg .u64 t; cvta.to.shared.u64 t, %1; cvt.u32.u64 %0, t; }" : "=r"(a) : "l"(p));
    return a;
}
__device__ __forceinline__ float rtf(float x) {
    uint32_t u;
    asm("cvt.rna.tf32.f32 %0, %1;" : "=r"(u) : "f"(x));
    return __uint_as_float(u);
}
__device__ __forceinline__ float4 rtf4(float4 v) {
    v.x = rtf(v.x); v.y = rtf(v.y); v.z = rtf(v.z); v.w = rtf(v.w);
    return v;
}
#define CP_ASYNC16(s, g) \
    asm volatile("cp.async.cg.shared.global [%0], [%1], 16;" :: "r"(s), "l"(g))
#define CP_COMMIT() asm volatile("cp.async.commit_group;")
#define CP_WAIT0()  asm volatile("cp.async.wait_group 0;" ::: "memory")

// ---------------------------------------------------------------------------
// Pre-convert x and all W to tf32-rounded copies (one pass)
// ---------------------------------------------------------------------------
__global__ __launch_bounds__(256) void conv_tf32(
    const float* __restrict__ x,
    const float* __restrict__ Wq, const float* __restrict__ Wk,
    const float* __restrict__ Wv, const float* __restrict__ Wo)
{
    const int z = blockIdx.z;
    const float* src; float* dst; int n4;
    if (z == 0)      { src = x;  dst = g_xt;              n4 = NROWS * DD / 4; }
    else if (z == 1) { src = Wq; dst = g_wt4;             n4 = DD * DD / 4; }
    else if (z == 2) { src = Wk; dst = g_wt4 + DD * DD;   n4 = DD * DD / 4; }
    else if (z == 3) { src = Wv; dst = g_wt4 + 2*DD*DD;   n4 = DD * DD / 4; }
    else             { src = Wo; dst = g_wt4 + 3*DD*DD;   n4 = DD * DD / 4; }
    const int stride = gridDim.x * blockDim.x;
    for (int i = blockIdx.x * blockDim.x + threadIdx.x; i < n4; i += stride)
        *(float4*)&dst[i * 4] = rtf4(*(const float4*)&src[i * 4]);
}

// ---------------------------------------------------------------------------
// tf32 WMMA GEMM — inputs pre-rounded, NO cvt in mainloop.
// CTA 128x128, BK=32, 256 thr, 8 warps (2m x 4n).
// ---------------------------------------------------------------------------
#define AS_STRIDE 36
#define BS_STRIDE 136
#define AS_FLOATS (128 * AS_STRIDE)
#define BS_FLOATS (32 * BS_STRIDE)
#define SMEM_BYTES  (2 * (AS_FLOATS + BS_FLOATS) * 4)   // 71680
#define ST_STRIDE 132

template<bool SCATTER>
__global__ __launch_bounds__(256, 2) void gemm_wmma(
    const float* __restrict__ bi0, const float* __restrict__ bi1, const float* __restrict__ bi2,
    float* __restrict__ Yout)
{
    extern __shared__ float smem[];
    float* sA = smem;
    float* sB = smem + 2 * AS_FLOATS;

    const int tid  = threadIdx.x;
    const int wid  = tid >> 5;
    const int wm   = wid & 1;
    const int wn   = wid >> 1;

    // All operand pointers bound device-side.
    const float* __restrict__ A = SCATTER ? g_xt : g_ctx;
    const float* __restrict__ W;
    const float* __restrict__ bias;
    float* __restrict__ outp;
    if (SCATTER) {
        const int z = blockIdx.z;
        W    = g_wt4 + (size_t)z * DD * DD;
        bias = (z == 0) ? bi0 : (z == 1) ? bi1 : bi2;
        outp = (z == 0) ? g_q : (z == 1) ? g_k : g_v;
    } else {
        W = g_wt4 + (size_t)3 * DD * DD; bias = bi0; outp = Yout;
    }

    const int rowBase = blockIdx.y * 128;
    const int colBase = blockIdx.x * 128;

    wmma::fragment<wmma::accumulator, 16, 16, 8, float> acc[4][2];
#pragma unroll
    for (int mt = 0; mt < 4; mt++)
#pragma unroll
        for (int nt = 0; nt < 2; nt++)
            wmma::fill_fragment(acc[mt][nt], 0.f);

    const uint32_t sAu = smem_u32(sA);
    const uint32_t sBu = smem_u32(sB);

    auto load_tile = [&](int it, int buf) {
        const int k0 = it * 32;
        uint32_t aBase = sAu + buf * AS_FLOATS * 4;
        uint32_t bBase = sBu + buf * BS_FLOATS * 4;
#pragma unroll
        for (int i = 0; i < 4; i++) {
            int ch = tid + i * 256;
            int m = ch >> 3, kq = ch & 7;
            CP_ASYNC16(aBase + (m * AS_STRIDE + kq * 4) * 4,
                       &A[(size_t)(rowBase + m) * DD + k0 + kq * 4]);
        }
#pragma unroll
        for (int i = 0; i < 4; i++) {
            int ch = tid + i * 256;
            int kk = ch >> 5, nq = ch & 31;
            CP_ASYNC16(bBase + (kk * BS_STRIDE + nq * 4) * 4,
                       &W[(size_t)(k0 + kk) * DD + colBase + nq * 4]);
        }
        CP_COMMIT();
    };

    load_tile(0, 0);
    CP_WAIT0();
    __syncthreads();

    const int NT = DD / 32;
    for (int it = 0; it < NT; it++) {
        const int buf = it & 1;
        if (it + 1 < NT) load_tile(it + 1, buf ^ 1);

        const float* As = sA + buf * AS_FLOATS;
        const float* Bs = sB + buf * BS_FLOATS;

#pragma unroll
        for (int ks = 0; ks < 4; ks++) {
            const int k = ks * 8;
            wmma::fragment<wmma::matrix_a, 16, 16, 8, wmma::precision::tf32, wmma::row_major> af[4];
            wmma::fragment<wmma::matrix_b, 16, 16, 8, wmma::precision::tf32, wmma::row_major> bf[2];
#pragma unroll
            for (int mt = 0; mt < 4; mt++)
                wmma::load_matrix_sync(af[mt], As + (wm * 64 + mt * 16) * AS_STRIDE + k, AS_STRIDE);
#pragma unroll
            for (int nt = 0; nt < 2; nt++)
                wmma::load_matrix_sync(bf[nt], Bs + k * BS_STRIDE + wn * 32 + nt * 16, BS_STRIDE);
#pragma unroll
            for (int mt = 0; mt < 4; mt++)
#pragma unroll
                for (int nt = 0; nt < 2; nt++)
                    wmma::mma_sync(acc[mt][nt], af[mt], bf[nt], acc[mt][nt]);
        }

        if (it + 1 < NT) CP_WAIT0();
        __syncthreads();
    }

    float* stage = smem;
#pragma unroll
    for (int mt = 0; mt < 4; mt++)
#pragma unroll
        for (int nt = 0; nt < 2; nt++)
            wmma::store_matrix_sync(stage + (wm * 64 + mt * 16) * ST_STRIDE + wn * 32 + nt * 16,
                                    acc[mt][nt], ST_STRIDE, wmma::mem_row_major);
    __syncthreads();

    const int rr   = tid >> 1;
    const int half = tid & 1;
    const int row  = rowBase + rr;
    const int bb   = row >> 11;
    const int s    = row & (SS - 1);
    if (SCATTER) {
        const int colG = colBase + half * 64;
        const int h = colG >> 6;
        float* dst = &outp[(((size_t)(bb * HH + h)) * SS + s) * HD];
#pragma unroll
        for (int j = 0; j < 16; j++) {
            const int cl = half * 64 + j * 4;
            float4 v  = *(const float4*)&stage[rr * ST_STRIDE + cl];
            float4 bv = *(const float4*)&bias[colBase + cl];
            v.x += bv.x; v.y += bv.y; v.z += bv.z; v.w += bv.w;
            *(float4*)&dst[j * 4] = rtf4(v);    // round: consumed by attn MMAs
        }
    } else {
        float* dst = &outp[(size_t)row * DD + colBase];
#pragma unroll
        for (int j = 0; j < 16; j++) {
            const int cl = half * 64 + j * 4;
            float4 v  = *(const float4*)&stage[rr * ST_STRIDE + cl];
            float4 bv = *(const float4*)&bias[colBase + cl];
            v.x += bv.x; v.y += bv.y; v.z += bv.z; v.w += bv.w;
            *(float4*)&dst[cl] = v;             // final output: full precision
        }
    }
}

// ---------------------------------------------------------------------------
// Tensor-core causal flash attention (no cvt in mainloop; inputs pre-rounded).
// CTA = (qt, bh): 64 q rows, 128 threads / 4 warps.
// ---------------------------------------------------------------------------
#define ATS 72
#define ATT_TILE_F (64 * ATS)
#define ATT_SMEM_BYTES ((5 * ATT_TILE_F + 128) * 4)   // 92672

__global__ __launch_bounds__(128) void attn_wmma()
{
    extern __shared__ float sm[];
    float* Qs = sm;
    float* Ks = Qs + ATT_TILE_F;
    float* Vs = Ks + ATT_TILE_F;
    float* SP = Vs + ATT_TILE_F;
    float* Os = SP + ATT_TILE_F;
    float* mrow = Os + ATT_TILE_F;   // 64
    float* lrow = mrow + 64;         // 64

    const int qt  = blockIdx.x;
    const int bh  = blockIdx.y;
    const int tid = threadIdx.x;
    const int wid = tid >> 5;

    const float* qbase = &g_q[((size_t)bh * SS + qt * 64) * HD];
    for (int i = tid; i < 1024; i += 128) {
        int r = i >> 4, c4 = (i & 15) * 4;
        float4 v = *(const float4*)&qbase[r * HD + c4];
        v.x *= 0.125f; v.y *= 0.125f; v.z *= 0.125f; v.w *= 0.125f;  // pow2: stays tf32
        *(float4*)&Qs[r * ATS + c4] = v;
        float4 z = {0.f, 0.f, 0.f, 0.f};
        *(float4*)&Os[r * ATS + c4] = z;
    }
    if (tid < 64) { mrow[tid] = -1e30f; lrow[tid] = 0.f; }
    __syncthreads();

    wmma::fragment<wmma::matrix_a, 16, 16, 8, wmma::precision::tf32, wmma::row_major> qf[8];
#pragma unroll
    for (int ks = 0; ks < 8; ks++)
        wmma::load_matrix_sync(qf[ks], Qs + (wid * 16) * ATS + ks * 8, ATS);

    for (int kt = 0; kt <= qt; kt++) {
        const float* kbase = &g_k[((size_t)bh * SS + kt * 64) * HD];
        const float* vbase = &g_v[((size_t)bh * SS + kt * 64) * HD];
        for (int i = tid; i < 1024; i += 128) {
            int r = i >> 4, c4 = (i & 15) * 4;
            *(float4*)&Ks[r * ATS + c4] = *(const float4*)&kbase[r * HD + c4];
            *(float4*)&Vs[r * ATS + c4] = *(const float4*)&vbase[r * HD + c4];
        }
        __syncthreads();

        // S = Q @ K^T
        {
            wmma::fragment<wmma::accumulator, 16, 16, 8, float> sacc[4];
#pragma unroll
            for (int nt = 0; nt < 4; nt++) wmma::fill_fragment(sacc[nt], 0.f);
#pragma unroll
            for (int ks = 0; ks < 8; ks++) {
#pragma unroll
                for (int nt = 0; nt < 4; nt++) {
                    wmma::fragment<wmma::matrix_b, 16, 16, 8, wmma::precision::tf32, wmma::col_major> kf;
                    wmma::load_matrix_sync(kf, Ks + (nt * 16) * ATS + ks * 8, ATS);
                    wmma::mma_sync(sacc[nt], qf[ks], kf, sacc[nt]);
                }
            }
#pragma unroll
            for (int nt = 0; nt < 4; nt++)
                wmma::store_matrix_sync(SP + (wid * 16) * ATS + nt * 16, sacc[nt],
                                        ATS, wmma::mem_row_major);
        }
        __syncthreads();

        // Online softmax: 2 threads per row (32 cols each), shfl-combined
        {
            const int row  = tid >> 1;
            const int half = tid & 1;
            float* srow = SP + row * ATS + half * 32;
            const int jmaxRow = (kt == qt) ? (row + 1) : 64;
            int lim = jmaxRow - half * 32;
            lim = (lim < 0) ? 0 : (lim > 32 ? 32 : lim);

            float mx = -1e30f;
#pragma unroll 8
            for (int j = 0; j < 32; j++)
                if (j < lim) mx = fmaxf(mx, srow[j]);
            mx = fmaxf(mx, __shfl_xor_sync(0xffffffffu, mx, 1));
            const float mold = mrow[row];
            mx = fmaxf(mx, mold);
            const float alpha = __expf(mold - mx);

            float sum = 0.f;
#pragma unroll 8
            for (int j = 0; j < 32; j++) {
                float p = (j < lim) ? rtf(__expf(srow[j] - mx)) : 0.f;
                srow[j] = p;
                sum += p;
            }
            sum += __shfl_xor_sync(0xffffffffu, sum, 1);
            if (half == 0) { lrow[row] = lrow[row] * alpha + sum; mrow[row] = mx; }

            float* orow = Os + row * ATS + half * 32;
#pragma unroll
            for (int d = 0; d < 32; d += 4) {
                float4 o4 = *(float4*)&orow[d];
                o4.x *= alpha; o4.y *= alpha; o4.z *= alpha; o4.w *= alpha;
                *(float4*)&orow[d] = o4;
            }
        }
        __syncthreads();

        // O += P @ V
        {
            wmma::fragment<wmma::matrix_a, 16, 16, 8, wmma::precision::tf32, wmma::row_major> pf[8];
#pragma unroll
            for (int ks = 0; ks < 8; ks++)
                wmma::load_matrix_sync(pf[ks], SP + (wid * 16) * ATS + ks * 8, ATS);
#pragma unroll
            for (int nt = 0; nt < 4; nt++) {
                wmma::fragment<wmma::accumulator, 16, 16, 8, float> of;
                wmma::load_matrix_sync(of, Os + (wid * 16) * ATS + nt * 16, ATS, wmma::mem_row_major);
#pragma unroll
                for (int ks = 0; ks < 8; ks++) {
                    wmma::fragment<wmma::matrix_b, 16, 16, 8, wmma::precision::tf32, wmma::row_major> vf;
                    wmma::load_matrix_sync(vf, Vs + (ks * 8) * ATS + nt * 16, ATS);
                    wmma::mma_sync(of, pf[ks], vf, of);
                }
                wmma::store_matrix_sync(Os + (wid * 16) * ATS + nt * 16, of, ATS, wmma::mem_row_major);
            }
        }
        __syncthreads();
    }

    // Normalize + write ctx (tf32-rounded: consumed by out-proj MMA)
    const int row  = tid >> 1;
    const int half = tid & 1;
    const float inv = 1.f / lrow[row];
    const int b = bh / HH, h = bh % HH;
    float* crow = &g_ctx[((size_t)b * SS + qt * 64 + row) * DD + h * HD + half * 32];
    const float* orow = Os + row * ATS + half * 32;
#pragma unroll
    for (int d = 0; d < 32; d += 4) {
        float4 o4 = *(const float4*)&orow[d];
        o4.x *= inv; o4.y *= inv; o4.z *= inv; o4.w *= inv;
        *(float4*)&crow[d] = rtf4(o4);
    }
}

// ---------------------------------------------------------------------------
extern "C" void kernel_launch(void* const* d_in, const int* in_sizes, int n_in,
                              void* d_out, int out_size)
{
    const float* x  = (const float*)d_in[0];
    const float* Wq = (const float*)d_in[1];
    const float* bq = (const float*)d_in[2];
    const float* Wk = (const float*)d_in[3];
    const float* bk = (const float*)d_in[4];
    const float* Wv = (const float*)d_in[5];
    const float* bv = (const float*)d_in[6];
    const float* Wo = (const float*)d_in[7];
    const float* bo = (const float*)d_in[8];
    float* out = (float*)d_out;

    cudaFuncSetAttribute(gemm_wmma<true>,  cudaFuncAttributeMaxDynamicSharedMemorySize, SMEM_BYTES);
    cudaFuncSetAttribute(gemm_wmma<false>, cudaFuncAttributeMaxDynamicSharedMemorySize, SMEM_BYTES);
    cudaFuncSetAttribute(attn_wmma, cudaFuncAttributeMaxDynamicSharedMemorySize, ATT_SMEM_BYTES);

    conv_tf32<<<dim3(512, 1, 5), 256>>>(x, Wq, Wk, Wv, Wo);

    dim3 gqkv(DD / 128, NROWS / 128, 3);
    gemm_wmma<true><<<gqkv, 256, SMEM_BYTES>>>(bq, bk, bv, nullptr);

    dim3 gattn(SS / 64, BB * HH);
    attn_wmma<<<gattn, 128, ATT_SMEM_BYTES>>>();

    dim3 gout(DD / 128, NROWS / 128);
    gemm_wmma<false><<<gout, 256, SMEM_BYTES>>>(bo, nullptr, nullptr, out);
}

// round 12
// speedup vs baseline: 1.5957x; 1.0121x over previous
#include <cuda_runtime.h>
#include <cstdint>
#include <mma.h>

using namespace nvcuda;

#define BB 2
#define SS 2048
#define DD 1024
#define HH 16
#define HD 64
#define NROWS (BB*SS)

__device__ float g_q[NROWS*DD];        // [B,H,S,HD]  (tf32-rounded)
__device__ float g_k[NROWS*DD];        // [B,H,S,HD]  (tf32-rounded)
__device__ float g_v[NROWS*DD];        // [B,H,S,HD]  (tf32-rounded)
__device__ float g_ctx[NROWS*DD];      // [B,S,D]     (tf32-rounded)
__device__ float g_xt[NROWS*DD];       // tf32(x)
__device__ float g_wt4[4*DD*DD];       // tf32(Wq,Wk,Wv,Wo)

__device__ __forceinline__ uint32_t smem_u32(const void* p) {
    uint32_t a;
    asm("{ .reg .u64 t; cvta.to.shared.u64 t, %1; cvt.u32.u64 %0, t; }" : "=r"(a) : "l"(p));
    return a;
}
__device__ __forceinline__ float rtf(float x) {
    uint32_t u;
    asm("cvt.rna.tf32.f32 %0, %1;" : "=r"(u) : "f"(x));
    return __uint_as_float(u);
}
__device__ __forceinline__ float4 rtf4(float4 v) {
    v.x = rtf(v.x); v.y = rtf(v.y); v.z = rtf(v.z); v.w = rtf(v.w);
    return v;
}
#define CP_ASYNC16(s, g) \
    asm volatile("cp.async.cg.shared.global [%0], [%1], 16;" :: "r"(s), "l"(g))
#define CP_COMMIT() asm volatile("cp.async.commit_group;")
#define CP_WAIT0()  asm volatile("cp.async.wait_group 0;" ::: "memory")

// ---------------------------------------------------------------------------
// Pre-convert x and all W to tf32-rounded copies
// ---------------------------------------------------------------------------
__global__ __launch_bounds__(256) void conv_tf32(
    const float* __restrict__ x,
    const float* __restrict__ Wq, const float* __restrict__ Wk,
    const float* __restrict__ Wv, const float* __restrict__ Wo)
{
    const int z = blockIdx.z;
    const float* src; float* dst; int n4;
    if (z == 0)      { src = x;  dst = g_xt;              n4 = NROWS * DD / 4; }
    else if (z == 1) { src = Wq; dst = g_wt4;             n4 = DD * DD / 4; }
    else if (z == 2) { src = Wk; dst = g_wt4 + DD * DD;   n4 = DD * DD / 4; }
    else if (z == 3) { src = Wv; dst = g_wt4 + 2*DD*DD;   n4 = DD * DD / 4; }
    else             { src = Wo; dst = g_wt4 + 3*DD*DD;   n4 = DD * DD / 4; }
    const int stride = gridDim.x * blockDim.x;
    for (int i = blockIdx.x * blockDim.x + threadIdx.x; i < n4; i += stride)
        *(float4*)&dst[i * 4] = rtf4(*(const float4*)&src[i * 4]);
}

// ---------------------------------------------------------------------------
// tf32 WMMA GEMM (unchanged from R10)
// ---------------------------------------------------------------------------
#define AS_STRIDE 36
#define BS_STRIDE 136
#define AS_FLOATS (128 * AS_STRIDE)
#define BS_FLOATS (32 * BS_STRIDE)
#define SMEM_BYTES  (2 * (AS_FLOATS + BS_FLOATS) * 4)   // 71680
#define ST_STRIDE 132

template<bool SCATTER>
__global__ __launch_bounds__(256, 2) void gemm_wmma(
    const float* __restrict__ bi0, const float* __restrict__ bi1, const float* __restrict__ bi2,
    float* __restrict__ Yout)
{
    extern __shared__ float smem[];
    float* sA = smem;
    float* sB = smem + 2 * AS_FLOATS;

    const int tid  = threadIdx.x;
    const int wid  = tid >> 5;
    const int wm   = wid & 1;
    const int wn   = wid >> 1;

    const float* __restrict__ A = SCATTER ? g_xt : g_ctx;
    const float* __restrict__ W;
    const float* __restrict__ bias;
    float* __restrict__ outp;
    if (SCATTER) {
        const int z = blockIdx.z;
        W    = g_wt4 + (size_t)z * DD * DD;
        bias = (z == 0) ? bi0 : (z == 1) ? bi1 : bi2;
        outp = (z == 0) ? g_q : (z == 1) ? g_k : g_v;
    } else {
        W = g_wt4 + (size_t)3 * DD * DD; bias = bi0; outp = Yout;
    }

    const int rowBase = blockIdx.y * 128;
    const int colBase = blockIdx.x * 128;

    wmma::fragment<wmma::accumulator, 16, 16, 8, float> acc[4][2];
#pragma unroll
    for (int mt = 0; mt < 4; mt++)
#pragma unroll
        for (int nt = 0; nt < 2; nt++)
            wmma::fill_fragment(acc[mt][nt], 0.f);

    const uint32_t sAu = smem_u32(sA);
    const uint32_t sBu = smem_u32(sB);

    auto load_tile = [&](int it, int buf) {
        const int k0 = it * 32;
        uint32_t aBase = sAu + buf * AS_FLOATS * 4;
        uint32_t bBase = sBu + buf * BS_FLOATS * 4;
#pragma unroll
        for (int i = 0; i < 4; i++) {
            int ch = tid + i * 256;
            int m = ch >> 3, kq = ch & 7;
            CP_ASYNC16(aBase + (m * AS_STRIDE + kq * 4) * 4,
                       &A[(size_t)(rowBase + m) * DD + k0 + kq * 4]);
        }
#pragma unroll
        for (int i = 0; i < 4; i++) {
            int ch = tid + i * 256;
            int kk = ch >> 5, nq = ch & 31;
            CP_ASYNC16(bBase + (kk * BS_STRIDE + nq * 4) * 4,
                       &W[(size_t)(k0 + kk) * DD + colBase + nq * 4]);
        }
        CP_COMMIT();
    };

    load_tile(0, 0);
    CP_WAIT0();
    __syncthreads();

    const int NT = DD / 32;
    for (int it = 0; it < NT; it++) {
        const int buf = it & 1;
        if (it + 1 < NT) load_tile(it + 1, buf ^ 1);

        const float* As = sA + buf * AS_FLOATS;
        const float* Bs = sB + buf * BS_FLOATS;

#pragma unroll
        for (int ks = 0; ks < 4; ks++) {
            const int k = ks * 8;
            wmma::fragment<wmma::matrix_a, 16, 16, 8, wmma::precision::tf32, wmma::row_major> af[4];
            wmma::fragment<wmma::matrix_b, 16, 16, 8, wmma::precision::tf32, wmma::row_major> bf[2];
#pragma unroll
            for (int mt = 0; mt < 4; mt++)
                wmma::load_matrix_sync(af[mt], As + (wm * 64 + mt * 16) * AS_STRIDE + k, AS_STRIDE);
#pragma unroll
            for (int nt = 0; nt < 2; nt++)
                wmma::load_matrix_sync(bf[nt], Bs + k * BS_STRIDE + wn * 32 + nt * 16, BS_STRIDE);
#pragma unroll
            for (int mt = 0; mt < 4; mt++)
#pragma unroll
                for (int nt = 0; nt < 2; nt++)
                    wmma::mma_sync(acc[mt][nt], af[mt], bf[nt], acc[mt][nt]);
        }

        if (it + 1 < NT) CP_WAIT0();
        __syncthreads();
    }

    float* stage = smem;
#pragma unroll
    for (int mt = 0; mt < 4; mt++)
#pragma unroll
        for (int nt = 0; nt < 2; nt++)
            wmma::store_matrix_sync(stage + (wm * 64 + mt * 16) * ST_STRIDE + wn * 32 + nt * 16,
                                    acc[mt][nt], ST_STRIDE, wmma::mem_row_major);
    __syncthreads();

    const int rr   = tid >> 1;
    const int half = tid & 1;
    const int row  = rowBase + rr;
    const int bb   = row >> 11;
    const int s    = row & (SS - 1);
    if (SCATTER) {
        const int colG = colBase + half * 64;
        const int h = colG >> 6;
        float* dst = &outp[(((size_t)(bb * HH + h)) * SS + s) * HD];
#pragma unroll
        for (int j = 0; j < 16; j++) {
            const int cl = half * 64 + j * 4;
            float4 v  = *(const float4*)&stage[rr * ST_STRIDE + cl];
            float4 bv = *(const float4*)&bias[colBase + cl];
            v.x += bv.x; v.y += bv.y; v.z += bv.z; v.w += bv.w;
            *(float4*)&dst[j * 4] = rtf4(v);
        }
    } else {
        float* dst = &outp[(size_t)row * DD + colBase];
#pragma unroll
        for (int j = 0; j < 16; j++) {
            const int cl = half * 64 + j * 4;
            float4 v  = *(const float4*)&stage[rr * ST_STRIDE + cl];
            float4 bv = *(const float4*)&bias[colBase + cl];
            v.x += bv.x; v.y += bv.y; v.z += bv.z; v.w += bv.w;
            *(float4*)&dst[cl] = v;
        }
    }
}

// ---------------------------------------------------------------------------
// Tensor-core causal flash attention v3.
// CTA = (qt, bh): 64 q rows, 256 threads / 8 warps (4m x 2n).
// cp.async double-buffered K/V; 4-thread-per-row softmax; heavy-first order.
// ---------------------------------------------------------------------------
#define ATS 72
#define ATT_TILE_F (64 * ATS)
// Qs, Os, SP, K0, K1, V0, V1 = 7 tiles + 128 floats
#define ATT_SMEM_BYTES ((7 * ATT_TILE_F + 128) * 4)   // 129536

__global__ __launch_bounds__(256) void attn_wmma()
{
    extern __shared__ float sm[];
    float* Qs = sm;
    float* Os = Qs + ATT_TILE_F;
    float* SP = Os + ATT_TILE_F;
    float* Kd[2] = { SP + ATT_TILE_F, SP + 2 * ATT_TILE_F };
    float* Vd[2] = { SP + 3 * ATT_TILE_F, SP + 4 * ATT_TILE_F };
    float* mrow = SP + 5 * ATT_TILE_F;   // 64
    float* lrow = mrow + 64;             // 64

    const int qt  = (int)gridDim.x - 1 - (int)blockIdx.x;   // heavy CTAs first
    const int bh  = blockIdx.y;
    const int tid = threadIdx.x;
    const int wid = tid >> 5;
    const int wm  = wid & 3;             // 0..3 : rows wm*16
    const int wn  = wid >> 2;            // 0..1 : cols wn*32

    const uint32_t ku[2] = { smem_u32(Kd[0]), smem_u32(Kd[1]) };
    const uint32_t vu[2] = { smem_u32(Vd[0]), smem_u32(Vd[1]) };

    const float* kbase0 = &g_k[((size_t)bh * SS) * HD];
    const float* vbase0 = &g_v[((size_t)bh * SS) * HD];

    auto issue_tile = [&](int kt, int buf) {
        const float* kb = kbase0 + (size_t)kt * 64 * HD;
        const float* vb = vbase0 + (size_t)kt * 64 * HD;
#pragma unroll
        for (int i = 0; i < 4; i++) {
            int ch = tid + i * 256;
            int r = ch >> 4, c4 = (ch & 15) * 4;
            CP_ASYNC16(ku[buf] + (r * ATS + c4) * 4, kb + r * HD + c4);
        }
#pragma unroll
        for (int i = 0; i < 4; i++) {
            int ch = tid + i * 256;
            int r = ch >> 4, c4 = (ch & 15) * 4;
            CP_ASYNC16(vu[buf] + (r * ATS + c4) * 4, vb + r * HD + c4);
        }
        CP_COMMIT();
    };

    // Prologue: issue tile 0, load Q (scaled), zero O, init m/l
    issue_tile(0, 0);
    const float* qbase = &g_q[((size_t)bh * SS + qt * 64) * HD];
    for (int i = tid; i < 1024; i += 256) {
        int r = i >> 4, c4 = (i & 15) * 4;
        float4 v = *(const float4*)&qbase[r * HD + c4];
        v.x *= 0.125f; v.y *= 0.125f; v.z *= 0.125f; v.w *= 0.125f;  // pow2: stays tf32
        *(float4*)&Qs[r * ATS + c4] = v;
        float4 z = {0.f, 0.f, 0.f, 0.f};
        *(float4*)&Os[r * ATS + c4] = z;
    }
    if (tid < 64) { mrow[tid] = -1e30f; lrow[tid] = 0.f; }
    CP_WAIT0();
    __syncthreads();

    // Q fragments: rows wm*16, loaded once
    wmma::fragment<wmma::matrix_a, 16, 16, 8, wmma::precision::tf32, wmma::row_major> qf[8];
#pragma unroll
    for (int ks = 0; ks < 8; ks++)
        wmma::load_matrix_sync(qf[ks], Qs + (wm * 16) * ATS + ks * 8, ATS);

    for (int kt = 0; kt <= qt; kt++) {
        const int buf = kt & 1;
        if (kt < qt) issue_tile(kt + 1, buf ^ 1);   // overlaps with compute below

        const float* Ks = Kd[buf];
        const float* Vs = Vd[buf];

        // S = Q @ K^T  (warp computes 16x32 chunk)
        {
            wmma::fragment<wmma::accumulator, 16, 16, 8, float> sacc[2];
#pragma unroll
            for (int nt = 0; nt < 2; nt++) wmma::fill_fragment(sacc[nt], 0.f);
#pragma unroll
            for (int ks = 0; ks < 8; ks++) {
#pragma unroll
                for (int nt = 0; nt < 2; nt++) {
                    wmma::fragment<wmma::matrix_b, 16, 16, 8, wmma::precision::tf32, wmma::col_major> kf;
                    wmma::load_matrix_sync(kf, Ks + (wn * 32 + nt * 16) * ATS + ks * 8, ATS);
                    wmma::mma_sync(sacc[nt], qf[ks], kf, sacc[nt]);
                }
            }
#pragma unroll
            for (int nt = 0; nt < 2; nt++)
                wmma::store_matrix_sync(SP + (wm * 16) * ATS + wn * 32 + nt * 16, sacc[nt],
                                        ATS, wmma::mem_row_major);
        }
        __syncthreads();

        // Online softmax: 4 threads per row (16 cols each)
        {
            const int row = tid >> 2;
            const int qq  = tid & 3;
            float* srow = SP + row * ATS + qq * 16;
            const int jmaxRow = (kt == qt) ? (row + 1) : 64;
            int lim = jmaxRow - qq * 16;
            lim = (lim < 0) ? 0 : (lim > 16 ? 16 : lim);

            float mx = -1e30f;
#pragma unroll
            for (int j = 0; j < 16; j++)
                if (j < lim) mx = fmaxf(mx, srow[j]);
            mx = fmaxf(mx, __shfl_xor_sync(0xffffffffu, mx, 1));
            mx = fmaxf(mx, __shfl_xor_sync(0xffffffffu, mx, 2));
            const float mold = mrow[row];
            mx = fmaxf(mx, mold);
            const float alpha = __expf(mold - mx);

            float sum = 0.f;
#pragma unroll
            for (int j = 0; j < 16; j++) {
                float p = (j < lim) ? rtf(__expf(srow[j] - mx)) : 0.f;
                srow[j] = p;
                sum += p;
            }
            sum += __shfl_xor_sync(0xffffffffu, sum, 1);
            sum += __shfl_xor_sync(0xffffffffu, sum, 2);
            if (qq == 0) { lrow[row] = lrow[row] * alpha + sum; mrow[row] = mx; }

            float* orow = Os + row * ATS + qq * 16;
#pragma unroll
            for (int d = 0; d < 16; d += 4) {
                float4 o4 = *(float4*)&orow[d];
                o4.x *= alpha; o4.y *= alpha; o4.z *= alpha; o4.w *= alpha;
                *(float4*)&orow[d] = o4;
            }
        }
        __syncthreads();

        // O += P @ V  (warp computes 16x32 chunk)
        {
            wmma::fragment<wmma::matrix_a, 16, 16, 8, wmma::precision::tf32, wmma::row_major> pf[8];
#pragma unroll
            for (int ks = 0; ks < 8; ks++)
                wmma::load_matrix_sync(pf[ks], SP + (wm * 16) * ATS + ks * 8, ATS);
#pragma unroll
            for (int nt = 0; nt < 2; nt++) {
                wmma::fragment<wmma::accumulator, 16, 16, 8, float> of;
                wmma::load_matrix_sync(of, Os + (wm * 16) * ATS + wn * 32 + nt * 16, ATS, wmma::mem_row_major);
#pragma unroll
                for (int ks = 0; ks < 8; ks++) {
                    wmma::fragment<wmma::matrix_b, 16, 16, 8, wmma::precision::tf32, wmma::row_major> vf;
                    wmma::load_matrix_sync(vf, Vs + (ks * 8) * ATS + wn * 32 + nt * 16, ATS);
                    wmma::mma_sync(of, pf[ks], vf, of);
                }
                wmma::store_matrix_sync(Os + (wm * 16) * ATS + wn * 32 + nt * 16, of, ATS, wmma::mem_row_major);
            }
        }
        CP_WAIT0();            // next K/V tile landed
        __syncthreads();       // also orders PV-store vs next softmax
    }

    // Normalize + write ctx (tf32-rounded: consumed by out-proj MMA)
    const int row = tid >> 2;
    const int qq  = tid & 3;
    const float inv = 1.f / lrow[row];
    const int b = bh / HH, h = bh % HH;
    float* crow = &g_ctx[((size_t)b * SS + qt * 64 + row) * DD + h * HD + qq * 16];
    const float* orow = Os + row * ATS + qq * 16;
#pragma unroll
    for (int d = 0; d < 16; d += 4) {
        float4 o4 = *(const float4*)&orow[d];
        o4.x *= inv; o4.y *= inv; o4.z *= inv; o4.w *= inv;
        *(float4*)&crow[d] = rtf4(o4);
    }
}

// ---------------------------------------------------------------------------
extern "C" void kernel_launch(void* const* d_in, const int* in_sizes, int n_in,
                              void* d_out, int out_size)
{
    const float* x  = (const float*)d_in[0];
    const float* Wq = (const float*)d_in[1];
    const float* bq = (const float*)d_in[2];
    const float* Wk = (const float*)d_in[3];
    const float* bk = (const float*)d_in[4];
    const float* Wv = (const float*)d_in[5];
    const float* bv = (const float*)d_in[6];
    const float* Wo = (const float*)d_in[7];
    const float* bo = (const float*)d_in[8];
    float* out = (float*)d_out;

    cudaFuncSetAttribute(gemm_wmma<true>,  cudaFuncAttributeMaxDynamicSharedMemorySize, SMEM_BYTES);
    cudaFuncSetAttribute(gemm_wmma<false>, cudaFuncAttributeMaxDynamicSharedMemorySize, SMEM_BYTES);
    cudaFuncSetAttribute(attn_wmma, cudaFuncAttributeMaxDynamicSharedMemorySize, ATT_SMEM_BYTES);

    conv_tf32<<<dim3(512, 1, 5), 256>>>(x, Wq, Wk, Wv, Wo);

    dim3 gqkv(DD / 128, NROWS / 128, 3);
    gemm_wmma<true><<<gqkv, 256, SMEM_BYTES>>>(bq, bk, bv, nullptr);

    dim3 gattn(SS / 64, BB * HH);
    attn_wmma<<<gattn, 256, ATT_SMEM_BYTES>>>();

    dim3 gout(DD / 128, NROWS / 128);
    gemm_wmma<false><<<gout, 256, SMEM_BYTES>>>(bo, nullptr, nullptr, out);
}